// round 17
// baseline (speedup 1.0000x reference)
#include <cuda_runtime.h>

// out[b, p] = s[b, ROW[p]] * s[b, COL[p]],  s[b,f] = sum_e x[b,f,e]
// B=16384, F=32, E=64, P=496.
//
// Persistent kernel: grid = 912 CTAs (152 SMs x occ 6), 2 warps/CTA, each
// warp strides over batches. Per warp: double-buffered raw smem tile filled
// by cp.async.cg (LDGSTS: no dest register -> 16 copies of the NEXT batch
// are issued before the current batch is consumed, so the warp always has a
// full tile of loads in flight). Tile rows padded to 17x16B per field so the
// reduce-phase LDS.128 (lane f reads its whole field) is conflict-free at
// quarter-warp granularity. Then ssum -> 496 products via packed pair table,
// 4x STG.128.CS. All shared memory is static (36 KB), no attribute calls.

static constexpr int BATCH   = 16384;
static constexpr int FIELDS  = 32;
static constexpr int PAIRS_N = 496;
static constexpr int WPC     = 2;
static constexpr int THREADS = WPC * 32;        // 64
static constexpr int GRID    = 912;             // 152 SMs * occ 6, single wave
static constexpr int NWARPS  = GRID * WPC;      // 1824
static constexpr int TILE16  = FIELDS * 17;     // 544 16B-units = 8704 B padded

__device__ __forceinline__ void pair_from_p(int p, int& i, int& j) {
    i = (int)((63.0f - sqrtf(3969.0f - 8.0f * (float)p)) * 0.5f);
    if (i < 0) i = 0;
    if (i > 30) i = 30;
    while (i > 0 && (i * (63 - i)) / 2 > p) --i;
    while (((i + 1) * (62 - i)) / 2 <= p) ++i;
    j = p - (i * (63 - i)) / 2 + i + 1;
}

__device__ __forceinline__ void issue_batch(const float* __restrict__ x,
                                            int b, unsigned tile_sa, int lane) {
    // lane copies g = k*32 + lane (coalesced); padded dst unit = k*34 + lane + (lane>>4)
    const float4* src = reinterpret_cast<const float4*>(x) + (size_t)b * 512 + lane;
    unsigned dst = tile_sa + (unsigned)(lane + (lane >> 4)) * 16u;
    #pragma unroll
    for (int k = 0; k < 16; ++k) {
        asm volatile("cp.async.cg.shared.global [%0], [%1], 16;"
                     :: "r"(dst + (unsigned)(k * 34 * 16)), "l"(src + k * 32));
    }
    asm volatile("cp.async.commit_group;");
}

__global__ __launch_bounds__(THREADS, 6)
void opn_kernel(const float* __restrict__ x, float* __restrict__ out) {
    __shared__ unsigned short tab[512];            // packed (i | j<<8), 496 used
    __shared__ float ssum[WPC][FIELDS];
    __shared__ float4 tiles[WPC][2][TILE16];       // 2 x 2 x 8704 B

    const int t    = threadIdx.x;
    const int w    = t >> 5;
    const int lane = t & 31;

    // ---- build pair table: 64 threads x 8 entries ----
    #pragma unroll
    for (int q = 0; q < 8; ++q) {
        int p = 8 * t + q;
        if (p < PAIRS_N) {
            int i, j;
            pair_from_p(p, i, j);
            tab[p] = (unsigned short)(i | (j << 8));
        }
    }
    __syncthreads();   // table visible; warps fully independent afterward

    const unsigned tile_sa0 =
        (unsigned)__cvta_generic_to_shared(&tiles[w][0][0]);
    float* sw = ssum[w];

    int b  = blockIdx.x * WPC + w;
    int nb = b + NWARPS;
    int d  = 0;

    if (b < BATCH) issue_batch(x, b, tile_sa0, lane);

    while (b < BATCH) {
        // prefetch next batch into the other buffer, then wait for current
        if (nb < BATCH) {
            issue_batch(x, nb, tile_sa0 + (unsigned)((d ^ 1) * TILE16 * 16), lane);
            asm volatile("cp.async.wait_group 1;");
        } else {
            asm volatile("cp.async.wait_group 0;");
        }
        __syncwarp();

        // ---- reduce: lane f sums its field (16 conflict-free LDS.128) ----
        {
            const float4* tp = &tiles[w][d][lane * 17];
            float a0 = 0.f, a1 = 0.f, a2 = 0.f, a3 = 0.f;
            #pragma unroll
            for (int i = 0; i < 16; ++i) {
                float4 v = tp[i];
                a0 += v.x; a1 += v.y; a2 += v.z; a3 += v.w;
            }
            sw[lane] = (a0 + a1) + (a2 + a3);
        }
        __syncwarp();

        // ---- 496 products, 4 per thread per iter, STG.128.CS ----
        float* ob = out + (size_t)b * PAIRS_N;
        #pragma unroll
        for (int m = 0; m < 4; ++m) {
            int p = m * 128 + lane * 4;
            if (p < PAIRS_N) {
                ushort4 e = *reinterpret_cast<const ushort4*>(tab + p);
                float4 r;
                r.x = sw[e.x & 255] * sw[e.x >> 8];
                r.y = sw[e.y & 255] * sw[e.y >> 8];
                r.z = sw[e.z & 255] * sw[e.z >> 8];
                r.w = sw[e.w & 255] * sw[e.w >> 8];
                __stcs(reinterpret_cast<float4*>(ob + p), r);
            }
        }
        __syncwarp();   // all lanes done reading buffer d before it refills

        b = nb; nb += NWARPS; d ^= 1;
    }
}

extern "C" void kernel_launch(void* const* d_in, const int* in_sizes, int n_in,
                              void* d_out, int out_size) {
    const float* x = (const float*)d_in[0];
    float* out = (float*)d_out;
    opn_kernel<<<GRID, THREADS>>>(x, out);
}